// round 2
// baseline (speedup 1.0000x reference)
#include <cuda_runtime.h>
#include <float.h>
#include <stdint.h>

#define Bsz  8
#define Cdim 128
#define Ndim 4096
#define Odim 256
#define KNN  16

// ---------------- scratch (static device globals; no allocations) -------------
__device__ float g_net[Bsz * Cdim * Ndim];     // [b][c][n]      16 MB
__device__ float g_sq[Bsz * Ndim];             // [b][n]
__device__ int   g_idx[Bsz * Ndim * KNN];      // [b][n][k]       2 MB
__device__ float g_p1t[Bsz * Ndim * Odim];     // [b][n][o]      32 MB (n-major!)
__device__ float g_baset[Bsz * Ndim * Odim];   // [b][n][o]      32 MB

// ---------------- packed f32x2 FMA (Blackwell) --------------------------------
__device__ __forceinline__ void fma2(unsigned long long& d, unsigned long long a,
                                     unsigned long long b, unsigned long long c) {
    asm("fma.rn.f32x2 %0, %1, %2, %3;" : "=l"(d) : "l"(a), "l"(b), "l"(c));
}
__device__ __forceinline__ unsigned long long pack2(float v) {
    unsigned long long r; unsigned u = __float_as_uint(v);
    asm("mov.b64 %0, {%1, %1};" : "=l"(r) : "r"(u));
    return r;
}

// ==============================================================================
// Kernel A: net = relu(w0 @ x + b0), fused sq[b][n] = sum_c net^2
// grid (32, 8), 256 threads. tx -> n (8 cols), ty -> o (8 rows)
// Weights staged per-K-chunk as Ws[c][o] (32x128, padded) -- fits 48KB static.
// ==============================================================================
__global__ __launch_bounds__(256) void k_net(const float* __restrict__ x,
                                             const float* __restrict__ w0,
                                             const float* __restrict__ b0) {
    __shared__ float Ws[32][129];   // [c-chunk][o], padded (scalar reads only)
    __shared__ float Ns[32][128];   // [c-chunk][n], unpadded (float4 reads)
    __shared__ float sqs[16][129];

    const int b  = blockIdx.y;
    const int n0 = blockIdx.x * 128;
    const int tid = threadIdx.x;
    const int tx = tid & 15;        // n group
    const int ty = tid >> 4;        // o group

    float acc[8][8];
    #pragma unroll
    for (int i = 0; i < 8; ++i)
        #pragma unroll
        for (int j = 0; j < 8; ++j) acc[i][j] = 0.f;

    for (int k0 = 0; k0 < 128; k0 += 32) {
        __syncthreads();
        // stage W chunk: Ws[cc][o] = w0[o][k0+cc]  (coalesced gmem: lanes -> cc)
        #pragma unroll
        for (int i = 0; i < 16; ++i) {
            int idx = tid + i * 256;
            int cc = idx & 31, o = idx >> 5;
            Ws[cc][o] = w0[o * 128 + k0 + cc];
        }
        // stage x chunk
        #pragma unroll
        for (int i = 0; i < 16; ++i) {
            int idx = tid + i * 256;
            int c = idx >> 7, n = idx & 127;
            Ns[c][n] = x[(b * 128 + k0 + c) * Ndim + n0 + n];
        }
        __syncthreads();
        #pragma unroll
        for (int kk = 0; kk < 32; ++kk) {
            float4 x0 = *(const float4*)&Ns[kk][tx * 8];
            float4 x1 = *(const float4*)&Ns[kk][tx * 8 + 4];
            float xr[8] = {x0.x, x0.y, x0.z, x0.w, x1.x, x1.y, x1.z, x1.w};
            #pragma unroll
            for (int i = 0; i < 8; ++i) {
                float wv = Ws[kk][ty * 8 + i];
                #pragma unroll
                for (int j = 0; j < 8; ++j) acc[i][j] += wv * xr[j];
            }
        }
    }

    float part[8];
    #pragma unroll
    for (int j = 0; j < 8; ++j) part[j] = 0.f;

    #pragma unroll
    for (int i = 0; i < 8; ++i) {
        int o = ty * 8 + i;
        float bv = __ldg(&b0[o]);
        float r[8];
        #pragma unroll
        for (int j = 0; j < 8; ++j) {
            r[j] = fmaxf(acc[i][j] + bv, 0.f);
            part[j] += r[j] * r[j];
        }
        int base = (b * 128 + o) * Ndim + n0 + tx * 8;
        float4 s0 = {r[0], r[1], r[2], r[3]};
        float4 s1 = {r[4], r[5], r[6], r[7]};
        *(float4*)&g_net[base]     = s0;
        *(float4*)&g_net[base + 4] = s1;
    }
    #pragma unroll
    for (int j = 0; j < 8; ++j) sqs[ty][tx * 8 + j] = part[j];
    __syncthreads();
    if (tid < 128) {
        float s = 0.f;
        #pragma unroll
        for (int r = 0; r < 16; ++r) s += sqs[r][tid];
        g_sq[b * Ndim + n0 + tid] = s;
    }
}

// ==============================================================================
// Kernel C: kNN. One thread per query; f32x2-packed gram; streaming top-17.
// grid (32, 8), 128 threads, dynamic smem 98560 B.
// ==============================================================================
__device__ __forceinline__ void topk_insert(float* kd, int* ki, float d, int m) {
    int j = 16;
    #pragma unroll 1
    while (j > 0 && kd[j - 1] > d) { kd[j] = kd[j - 1]; ki[j] = ki[j - 1]; --j; }
    kd[j] = d; ki[j] = m;
}

__global__ __launch_bounds__(128) void k_knn() {
    extern __shared__ float sm[];
    float* Qs  = sm;                 // [128 c][128 q]
    float* Ms  = sm + 128 * 128;     // [128 c][64 m]
    float* sqm = Ms + 128 * 64;      // [64]

    const int b  = blockIdx.y;
    const int n0 = blockIdx.x * 128;
    const int tid = threadIdx.x;     // query lane

    #pragma unroll 8
    for (int c = 0; c < 128; ++c)
        Qs[c * 128 + tid] = g_net[(b * 128 + c) * Ndim + n0 + tid];

    float kd[17]; int ki[17];
    #pragma unroll
    for (int i = 0; i < 17; ++i) { kd[i] = FLT_MAX; ki[i] = 0; }
    float worst = FLT_MAX;

    for (int mt = 0; mt < Ndim / 64; ++mt) {
        const int m0 = mt * 64;
        __syncthreads();
        #pragma unroll 8
        for (int i = 0; i < 64; ++i) {
            int idx = tid + i * 128;
            int c = idx >> 6, m = idx & 63;
            Ms[c * 64 + m] = g_net[(b * 128 + c) * Ndim + m0 + m];
        }
        if (tid < 64) sqm[tid] = g_sq[b * Ndim + m0 + tid];
        __syncthreads();

        unsigned long long acc[32];
        #pragma unroll
        for (int p = 0; p < 32; ++p) acc[p] = 0ull;

        #pragma unroll 2
        for (int c = 0; c < 128; ++c) {
            unsigned long long qp = pack2(Qs[c * 128 + tid]);
            const ulonglong2* mrow = (const ulonglong2*)(Ms + c * 64);
            #pragma unroll
            for (int p = 0; p < 16; ++p) {
                ulonglong2 v = mrow[p];
                fma2(acc[2 * p],     qp, v.x, acc[2 * p]);
                fma2(acc[2 * p + 1], qp, v.y, acc[2 * p + 1]);
            }
        }

        #pragma unroll
        for (int p = 0; p < 32; ++p) {
            unsigned long long a = acc[p];
            float d0 = __uint_as_float((unsigned)a);
            float d1 = __uint_as_float((unsigned)(a >> 32));
            int m = 2 * p;
            float key0 = sqm[m]     - 2.0f * d0;
            float key1 = sqm[m + 1] - 2.0f * d1;
            if (key0 < worst) { topk_insert(kd, ki, key0, m0 + m);     worst = kd[16]; }
            if (key1 < worst) { topk_insert(kd, ki, key1, m0 + m + 1); worst = kd[16]; }
        }
    }

    const int q = n0 + tid;
    #pragma unroll
    for (int t = 0; t < 16; ++t)
        g_idx[(b * Ndim + q) * KNN + t] = ki[t + 1];   // drop self (min)
}

// ==============================================================================
// Kernel D: p1 = w1@net ; base = w2@net + b1 + b2 - p1 ; both stored [b][n][o]
// grid (32, 8, 2), 256 threads. tx -> o (8), ty -> n (8)
// Weights staged per-K-chunk as [c][o] (16x128, padded).
// ==============================================================================
__global__ __launch_bounds__(256) void k_proj(const float* __restrict__ w1,
                                              const float* __restrict__ b1,
                                              const float* __restrict__ w2,
                                              const float* __restrict__ b2) {
    __shared__ float W1c[16][129];  // [c-chunk][o]
    __shared__ float W2c[16][129];
    __shared__ float Ns[16][128];   // [c-chunk][n]

    const int b  = blockIdx.y;
    const int n0 = blockIdx.x * 128;
    const int oz = blockIdx.z * 128;
    const int tid = threadIdx.x;
    const int tx = tid & 15;        // o group
    const int ty = tid >> 4;        // n group

    float a1[8][8], a2[8][8];       // [j=n][i=o]
    #pragma unroll
    for (int j = 0; j < 8; ++j)
        #pragma unroll
        for (int i = 0; i < 8; ++i) { a1[j][i] = 0.f; a2[j][i] = 0.f; }

    for (int k0 = 0; k0 < 128; k0 += 16) {
        __syncthreads();
        // stage weight chunks: [cc][o] = w[(oz+o)*128 + k0+cc]
        #pragma unroll
        for (int i = 0; i < 8; ++i) {
            int idx = tid + i * 256;
            int cc = idx & 15, o = idx >> 4;
            W1c[cc][o] = w1[(oz + o) * 128 + k0 + cc];
            W2c[cc][o] = w2[(oz + o) * 128 + k0 + cc];
        }
        #pragma unroll
        for (int i = 0; i < 8; ++i) {
            int idx = tid + i * 256;
            int c = idx >> 7, n = idx & 127;
            Ns[c][n] = g_net[(b * 128 + k0 + c) * Ndim + n0 + n];
        }
        __syncthreads();
        #pragma unroll
        for (int kk = 0; kk < 16; ++kk) {
            float4 nv0 = *(const float4*)&Ns[kk][ty * 8];
            float4 nv1 = *(const float4*)&Ns[kk][ty * 8 + 4];
            float nr[8] = {nv0.x, nv0.y, nv0.z, nv0.w, nv1.x, nv1.y, nv1.z, nv1.w};
            float w1r[8], w2r[8];
            #pragma unroll
            for (int i = 0; i < 8; ++i) {
                w1r[i] = W1c[kk][tx * 8 + i];
                w2r[i] = W2c[kk][tx * 8 + i];
            }
            #pragma unroll
            for (int j = 0; j < 8; ++j)
                #pragma unroll
                for (int i = 0; i < 8; ++i) {
                    a1[j][i] += nr[j] * w1r[i];
                    a2[j][i] += nr[j] * w2r[i];
                }
        }
    }

    float bb[8];
    #pragma unroll
    for (int i = 0; i < 8; ++i) {
        int o = oz + tx * 8 + i;
        bb[i] = __ldg(&b1[o]) + __ldg(&b2[o]);
    }
    #pragma unroll
    for (int j = 0; j < 8; ++j) {
        int n = n0 + ty * 8 + j;
        int base = (b * Ndim + n) * Odim + oz + tx * 8;
        float4 p0  = {a1[j][0], a1[j][1], a1[j][2], a1[j][3]};
        float4 p1v = {a1[j][4], a1[j][5], a1[j][6], a1[j][7]};
        *(float4*)&g_p1t[base]     = p0;
        *(float4*)&g_p1t[base + 4] = p1v;
        float4 e0 = {a2[j][0] + bb[0] - a1[j][0], a2[j][1] + bb[1] - a1[j][1],
                     a2[j][2] + bb[2] - a1[j][2], a2[j][3] + bb[3] - a1[j][3]};
        float4 e1 = {a2[j][4] + bb[4] - a1[j][4], a2[j][5] + bb[5] - a1[j][5],
                     a2[j][6] + bb[6] - a1[j][6], a2[j][7] + bb[7] - a1[j][7]};
        *(float4*)&g_baset[base]     = e0;
        *(float4*)&g_baset[base + 4] = e1;
    }
}

// ==============================================================================
// Kernel E: y[b,o,n] = relu(max_k (base[b,n,o] + p1t[b,idx[n,k],o]))
// grid (128, 8), 256 threads (thread = o). smem transpose for coalesced output.
// ==============================================================================
__global__ __launch_bounds__(256) void k_edge(float* __restrict__ out) {
    __shared__ int   idxs[32][16];
    __shared__ float ys[32][257];

    const int b  = blockIdx.y;
    const int n0 = blockIdx.x * 32;
    const int tid = threadIdx.x;

    #pragma unroll
    for (int i = 0; i < 2; ++i) {
        int j = tid + i * 256;
        idxs[j >> 4][j & 15] = g_idx[(b * Ndim + n0 + (j >> 4)) * KNN + (j & 15)];
    }
    __syncthreads();

    #pragma unroll 1
    for (int nn = 0; nn < 32; ++nn) {
        float v = g_baset[(b * Ndim + n0 + nn) * Odim + tid];
        float acc = -FLT_MAX;
        #pragma unroll
        for (int t = 0; t < 16; ++t) {
            int m = idxs[nn][t];
            acc = fmaxf(acc, v + g_p1t[(b * Ndim + m) * Odim + tid]);
        }
        ys[nn][tid] = fmaxf(acc, 0.f);
    }
    __syncthreads();

    #pragma unroll
    for (int i = 0; i < 32; ++i) {
        int j = tid + i * 256;
        int o = j >> 5, n = j & 31;
        out[(b * Odim + o) * Ndim + n0 + n] = ys[n][o];
    }
}

// ==============================================================================
extern "C" void kernel_launch(void* const* d_in, const int* in_sizes, int n_in,
                              void* d_out, int out_size) {
    // Assign pointers by element count (robust to metadata ordering).
    // x:4194304  w0:16384  b0:128  w1:32768(1st)  b1:256(1st)  w2:32768(2nd)  b2:256(2nd)
    const float *x = 0, *w0 = 0, *b0 = 0, *w1 = 0, *b1 = 0, *w2 = 0, *b2 = 0;
    for (int i = 0; i < n_in; ++i) {
        const float* p = (const float*)d_in[i];
        switch (in_sizes[i]) {
            case 4194304: x = p; break;
            case 16384:   w0 = p; break;
            case 128:     b0 = p; break;
            case 32768:   if (!w1) w1 = p; else w2 = p; break;
            case 256:     if (!b1) b1 = p; else b2 = p; break;
            default: break; // k, scale scalars
        }
    }
    float* out = (float*)d_out;

    const int knn_smem = (128 * 128 + 128 * 64 + 64) * (int)sizeof(float);
    cudaFuncSetAttribute(k_knn, cudaFuncAttributeMaxDynamicSharedMemorySize, knn_smem);

    k_net <<<dim3(32, 8),    256>>>(x, w0, b0);
    k_knn <<<dim3(32, 8),    128, knn_smem>>>();
    k_proj<<<dim3(32, 8, 2), 256>>>(w1, b1, w2, b2);
    k_edge<<<dim3(128, 8),   256>>>(out);
}

// round 3
// speedup vs baseline: 1.3060x; 1.3060x over previous
#include <cuda_runtime.h>
#include <float.h>
#include <stdint.h>

#define Bsz  8
#define Cdim 128
#define Ndim 4096
#define Odim 256
#define KNN  16

// ---------------- scratch (static device globals; no allocations) -------------
__device__ float g_net[Bsz * Cdim * Ndim];     // [b][c][n]      16 MB
__device__ float g_sq[Bsz * Ndim];             // [b][n]
__device__ int   g_idx[Bsz * Ndim * KNN];      // [b][n][k]       2 MB
__device__ float g_p1t[Bsz * Ndim * Odim];     // [b][n][o]      32 MB (n-major!)
__device__ float g_baset[Bsz * Ndim * Odim];   // [b][n][o]      32 MB

// ---------------- packed f32x2 FMA (Blackwell) --------------------------------
__device__ __forceinline__ void fma2(unsigned long long& d, unsigned long long a,
                                     unsigned long long b, unsigned long long c) {
    asm("fma.rn.f32x2 %0, %1, %2, %3;" : "=l"(d) : "l"(a), "l"(b), "l"(c));
}
__device__ __forceinline__ unsigned long long pack2(float v) {
    unsigned long long r; unsigned u = __float_as_uint(v);
    asm("mov.b64 %0, {%1, %1};" : "=l"(r) : "r"(u));
    return r;
}

// ==============================================================================
// Kernel A: net = relu(w0 @ x + b0), fused sq[b][n] = sum_c net^2
// ==============================================================================
__global__ __launch_bounds__(256) void k_net(const float* __restrict__ x,
                                             const float* __restrict__ w0,
                                             const float* __restrict__ b0) {
    __shared__ float Ws[32][129];   // [c-chunk][o], padded (scalar reads only)
    __shared__ float Ns[32][128];   // [c-chunk][n], unpadded (float4 reads)
    __shared__ float sqs[16][129];

    const int b  = blockIdx.y;
    const int n0 = blockIdx.x * 128;
    const int tid = threadIdx.x;
    const int tx = tid & 15;        // n group
    const int ty = tid >> 4;        // o group

    float acc[8][8];
    #pragma unroll
    for (int i = 0; i < 8; ++i)
        #pragma unroll
        for (int j = 0; j < 8; ++j) acc[i][j] = 0.f;

    for (int k0 = 0; k0 < 128; k0 += 32) {
        __syncthreads();
        #pragma unroll
        for (int i = 0; i < 16; ++i) {
            int idx = tid + i * 256;
            int cc = idx & 31, o = idx >> 5;
            Ws[cc][o] = w0[o * 128 + k0 + cc];
        }
        #pragma unroll
        for (int i = 0; i < 16; ++i) {
            int idx = tid + i * 256;
            int c = idx >> 7, n = idx & 127;
            Ns[c][n] = x[(b * 128 + k0 + c) * Ndim + n0 + n];
        }
        __syncthreads();
        #pragma unroll
        for (int kk = 0; kk < 32; ++kk) {
            float4 x0 = *(const float4*)&Ns[kk][tx * 8];
            float4 x1 = *(const float4*)&Ns[kk][tx * 8 + 4];
            float xr[8] = {x0.x, x0.y, x0.z, x0.w, x1.x, x1.y, x1.z, x1.w};
            #pragma unroll
            for (int i = 0; i < 8; ++i) {
                float wv = Ws[kk][ty * 8 + i];
                #pragma unroll
                for (int j = 0; j < 8; ++j) acc[i][j] += wv * xr[j];
            }
        }
    }

    float part[8];
    #pragma unroll
    for (int j = 0; j < 8; ++j) part[j] = 0.f;

    #pragma unroll
    for (int i = 0; i < 8; ++i) {
        int o = ty * 8 + i;
        float bv = __ldg(&b0[o]);
        float r[8];
        #pragma unroll
        for (int j = 0; j < 8; ++j) {
            r[j] = fmaxf(acc[i][j] + bv, 0.f);
            part[j] += r[j] * r[j];
        }
        int base = (b * 128 + o) * Ndim + n0 + tx * 8;
        float4 s0 = {r[0], r[1], r[2], r[3]};
        float4 s1 = {r[4], r[5], r[6], r[7]};
        *(float4*)&g_net[base]     = s0;
        *(float4*)&g_net[base + 4] = s1;
    }
    #pragma unroll
    for (int j = 0; j < 8; ++j) sqs[ty][tx * 8 + j] = part[j];
    __syncthreads();
    if (tid < 128) {
        float s = 0.f;
        #pragma unroll
        for (int r = 0; r < 16; ++r) s += sqs[r][tid];
        g_sq[b * Ndim + n0 + tid] = s;
    }
}

// ==============================================================================
// Kernel C v2: kNN via register-blocked gram (8q x 8m / thread, FFMA2 packed)
// grid (32, 8), 256 threads, dynamic smem 84480 B (2 blocks/SM).
// Per m-tile of 128: GEMM -> keys smem tile -> streaming top-17 scan.
// ==============================================================================
__device__ __forceinline__ void topk_insert(float* kd, int* ki, float d, int m) {
    int j = 16;
    #pragma unroll 1
    while (j > 0 && kd[j - 1] > d) { kd[j] = kd[j - 1]; ki[j] = ki[j - 1]; --j; }
    kd[j] = d; ki[j] = m;
}

#define KEYP 132   // keys row pitch (floats): 16B-aligned float4 stores

__global__ __launch_bounds__(256, 2) void k_knn() {
    extern __shared__ float sm[];
    float* Qc   = sm;                    // [16 cc][128 q]
    float* Mc   = sm + 2048;             // [16 cc][128 m]
    float* sqm  = sm + 4096;             // [128]
    float* keys = sm + 4224;             // [128 q][KEYP]

    const int b   = blockIdx.y;
    const int n0  = blockIdx.x * 128;    // query tile origin
    const int tid = threadIdx.x;
    const int tx  = tid & 15;            // q group (8 queries)
    const int ty  = tid >> 4;            // m group (8 points)

    float kd[17]; int ki[17];
    #pragma unroll
    for (int i = 0; i < 17; ++i) { kd[i] = FLT_MAX; ki[i] = 0; }
    float worst = FLT_MAX;

    for (int mt = 0; mt < 32; ++mt) {
        const int m0 = mt * 128;

        if (tid < 128) sqm[tid] = g_sq[b * Ndim + m0 + tid];

        unsigned long long acc[8][4];
        #pragma unroll
        for (int q = 0; q < 8; ++q)
            #pragma unroll
            for (int p = 0; p < 4; ++p) acc[q][p] = 0ull;

        for (int k0 = 0; k0 < 128; k0 += 16) {
            __syncthreads();
            #pragma unroll
            for (int i = 0; i < 8; ++i) {
                int idx = tid + i * 256;
                int cc = idx >> 7, e = idx & 127;
                Qc[cc * 128 + e] = g_net[(b * 128 + k0 + cc) * Ndim + n0 + e];
                Mc[cc * 128 + e] = g_net[(b * 128 + k0 + cc) * Ndim + m0 + e];
            }
            __syncthreads();
            #pragma unroll 4
            for (int cc = 0; cc < 16; ++cc) {
                float4 qa = *(const float4*)&Qc[cc * 128 + tx * 8];
                float4 qb = *(const float4*)&Qc[cc * 128 + tx * 8 + 4];
                unsigned long long qd[8] = {
                    pack2(qa.x), pack2(qa.y), pack2(qa.z), pack2(qa.w),
                    pack2(qb.x), pack2(qb.y), pack2(qb.z), pack2(qb.w)};
                ulonglong2 mA = *(const ulonglong2*)&Mc[cc * 128 + ty * 8];
                ulonglong2 mB = *(const ulonglong2*)&Mc[cc * 128 + ty * 8 + 4];
                unsigned long long mp[4] = {mA.x, mA.y, mB.x, mB.y};
                #pragma unroll
                for (int q = 0; q < 8; ++q)
                    #pragma unroll
                    for (int p = 0; p < 4; ++p)
                        fma2(acc[q][p], qd[q], mp[p], acc[q][p]);
            }
        }

        // epilogue: key = sq[m] - 2*dot -> keys[q][m]
        float sq8[8];
        #pragma unroll
        for (int j = 0; j < 8; ++j) sq8[j] = sqm[ty * 8 + j];
        #pragma unroll
        for (int q = 0; q < 8; ++q) {
            float kv[8];
            #pragma unroll
            for (int p = 0; p < 4; ++p) {
                unsigned long long a = acc[q][p];
                kv[2 * p]     = sq8[2 * p]     - 2.0f * __uint_as_float((unsigned)a);
                kv[2 * p + 1] = sq8[2 * p + 1] - 2.0f * __uint_as_float((unsigned)(a >> 32));
            }
            float4 v0 = {kv[0], kv[1], kv[2], kv[3]};
            float4 v1 = {kv[4], kv[5], kv[6], kv[7]};
            *(float4*)&keys[(tx * 8 + q) * KEYP + ty * 8]     = v0;
            *(float4*)&keys[(tx * 8 + q) * KEYP + ty * 8 + 4] = v1;
        }
        __syncthreads();

        // streaming top-17 scan (threads 0..127, one query each)
        if (tid < 128) {
            const float* krow = keys + tid * KEYP;
            #pragma unroll 4
            for (int m = 0; m < 128; ++m) {
                float kv = krow[m];
                if (kv < worst) { topk_insert(kd, ki, kv, m0 + m); worst = kd[16]; }
            }
        }
        __syncthreads();
    }

    if (tid < 128) {
        const int q = n0 + tid;
        #pragma unroll
        for (int t = 0; t < 16; ++t)
            g_idx[(b * Ndim + q) * KNN + t] = ki[t + 1];   // drop self (min)
    }
}

// ==============================================================================
// Kernel D: p1 = w1@net ; base = w2@net + b1 + b2 - p1 ; both stored [b][n][o]
// ==============================================================================
__global__ __launch_bounds__(256) void k_proj(const float* __restrict__ w1,
                                              const float* __restrict__ b1,
                                              const float* __restrict__ w2,
                                              const float* __restrict__ b2) {
    __shared__ float W1c[16][129];  // [c-chunk][o]
    __shared__ float W2c[16][129];
    __shared__ float Ns[16][128];   // [c-chunk][n]

    const int b  = blockIdx.y;
    const int n0 = blockIdx.x * 128;
    const int oz = blockIdx.z * 128;
    const int tid = threadIdx.x;
    const int tx = tid & 15;        // o group
    const int ty = tid >> 4;        // n group

    float a1[8][8], a2[8][8];       // [j=n][i=o]
    #pragma unroll
    for (int j = 0; j < 8; ++j)
        #pragma unroll
        for (int i = 0; i < 8; ++i) { a1[j][i] = 0.f; a2[j][i] = 0.f; }

    for (int k0 = 0; k0 < 128; k0 += 16) {
        __syncthreads();
        #pragma unroll
        for (int i = 0; i < 8; ++i) {
            int idx = tid + i * 256;
            int cc = idx & 15, o = idx >> 4;
            W1c[cc][o] = w1[(oz + o) * 128 + k0 + cc];
            W2c[cc][o] = w2[(oz + o) * 128 + k0 + cc];
        }
        #pragma unroll
        for (int i = 0; i < 8; ++i) {
            int idx = tid + i * 256;
            int c = idx >> 7, n = idx & 127;
            Ns[c][n] = g_net[(b * 128 + k0 + c) * Ndim + n0 + n];
        }
        __syncthreads();
        #pragma unroll
        for (int kk = 0; kk < 16; ++kk) {
            float4 nv0 = *(const float4*)&Ns[kk][ty * 8];
            float4 nv1 = *(const float4*)&Ns[kk][ty * 8 + 4];
            float nr[8] = {nv0.x, nv0.y, nv0.z, nv0.w, nv1.x, nv1.y, nv1.z, nv1.w};
            float w1r[8], w2r[8];
            #pragma unroll
            for (int i = 0; i < 8; ++i) {
                w1r[i] = W1c[kk][tx * 8 + i];
                w2r[i] = W2c[kk][tx * 8 + i];
            }
            #pragma unroll
            for (int j = 0; j < 8; ++j)
                #pragma unroll
                for (int i = 0; i < 8; ++i) {
                    a1[j][i] += nr[j] * w1r[i];
                    a2[j][i] += nr[j] * w2r[i];
                }
        }
    }

    float bb[8];
    #pragma unroll
    for (int i = 0; i < 8; ++i) {
        int o = oz + tx * 8 + i;
        bb[i] = __ldg(&b1[o]) + __ldg(&b2[o]);
    }
    #pragma unroll
    for (int j = 0; j < 8; ++j) {
        int n = n0 + ty * 8 + j;
        int base = (b * Ndim + n) * Odim + oz + tx * 8;
        float4 p0  = {a1[j][0], a1[j][1], a1[j][2], a1[j][3]};
        float4 p1v = {a1[j][4], a1[j][5], a1[j][6], a1[j][7]};
        *(float4*)&g_p1t[base]     = p0;
        *(float4*)&g_p1t[base + 4] = p1v;
        float4 e0 = {a2[j][0] + bb[0] - a1[j][0], a2[j][1] + bb[1] - a1[j][1],
                     a2[j][2] + bb[2] - a1[j][2], a2[j][3] + bb[3] - a1[j][3]};
        float4 e1 = {a2[j][4] + bb[4] - a1[j][4], a2[j][5] + bb[5] - a1[j][5],
                     a2[j][6] + bb[6] - a1[j][6], a2[j][7] + bb[7] - a1[j][7]};
        *(float4*)&g_baset[base]     = e0;
        *(float4*)&g_baset[base + 4] = e1;
    }
}

// ==============================================================================
// Kernel E: y[b,o,n] = relu(max_k (base[b,n,o] + p1t[b,idx[n,k],o]))
// ==============================================================================
__global__ __launch_bounds__(256) void k_edge(float* __restrict__ out) {
    __shared__ int   idxs[32][16];
    __shared__ float ys[32][257];

    const int b  = blockIdx.y;
    const int n0 = blockIdx.x * 32;
    const int tid = threadIdx.x;

    #pragma unroll
    for (int i = 0; i < 2; ++i) {
        int j = tid + i * 256;
        idxs[j >> 4][j & 15] = g_idx[(b * Ndim + n0 + (j >> 4)) * KNN + (j & 15)];
    }
    __syncthreads();

    #pragma unroll 1
    for (int nn = 0; nn < 32; ++nn) {
        float v = g_baset[(b * Ndim + n0 + nn) * Odim + tid];
        float acc = -FLT_MAX;
        #pragma unroll
        for (int t = 0; t < 16; ++t) {
            int m = idxs[nn][t];
            acc = fmaxf(acc, v + g_p1t[(b * Ndim + m) * Odim + tid]);
        }
        ys[nn][tid] = fmaxf(acc, 0.f);
    }
    __syncthreads();

    #pragma unroll
    for (int i = 0; i < 32; ++i) {
        int j = tid + i * 256;
        int o = j >> 5, n = j & 31;
        out[(b * Odim + o) * Ndim + n0 + n] = ys[n][o];
    }
}

// ==============================================================================
extern "C" void kernel_launch(void* const* d_in, const int* in_sizes, int n_in,
                              void* d_out, int out_size) {
    // Assign pointers by element count (robust to metadata ordering).
    const float *x = 0, *w0 = 0, *b0 = 0, *w1 = 0, *b1 = 0, *w2 = 0, *b2 = 0;
    for (int i = 0; i < n_in; ++i) {
        const float* p = (const float*)d_in[i];
        switch (in_sizes[i]) {
            case 4194304: x = p; break;
            case 16384:   w0 = p; break;
            case 128:     b0 = p; break;
            case 32768:   if (!w1) w1 = p; else w2 = p; break;
            case 256:     if (!b1) b1 = p; else b2 = p; break;
            default: break; // k, scale scalars
        }
    }
    float* out = (float*)d_out;

    const int knn_smem = (4224 + 128 * KEYP) * (int)sizeof(float);  // 84480 B
    cudaFuncSetAttribute(k_knn, cudaFuncAttributeMaxDynamicSharedMemorySize, knn_smem);

    k_net <<<dim3(32, 8),    256>>>(x, w0, b0);
    k_knn <<<dim3(32, 8),    256, knn_smem>>>();
    k_proj<<<dim3(32, 8, 2), 256>>>(w1, b1, w2, b2);
    k_edge<<<dim3(128, 8),   256>>>(out);
}